// round 5
// baseline (speedup 1.0000x reference)
#include <cuda_runtime.h>
#include <cuda_bf16.h>
#include <mma.h>

using namespace nvcuda;

#define MTOK 16384
#define NROW 3072
#define KDIM 1024

// ---- static device scratch (no allocations) ----
__device__ float         g_qkv[16 * 4 * 192 * 4096];   // [(h*4+b)*192 + j][s]
__device__ __nv_bfloat16 g_Wh[NROW * KDIM], g_Wl[NROW * KDIM];
__device__ __nv_bfloat16 g_Xh[(size_t)MTOK * KDIM], g_Xl[(size_t)MTOK * KDIM];
__device__ float         g_part[8 * 64 * 64 * 64];     // [chunk][hb][d][e]
__device__ float         g_probs[64 * 64 * 64];        // [hb][d][e]

__global__ void split_x(const float* __restrict__ s) {
    int i = blockIdx.x * blockDim.x + threadIdx.x;
    float v = s[i];
    __nv_bfloat16 h = __float2bfloat16(v);
    g_Xh[i] = h;
    g_Xl[i] = __float2bfloat16(v - __bfloat162float(h));
}
__global__ void split_w(const float* __restrict__ s) {
    int i = blockIdx.x * blockDim.x + threadIdx.x;
    float v = s[i];
    __nv_bfloat16 h = __float2bfloat16(v);
    g_Wh[i] = h;
    g_Wl[i] = __float2bfloat16(v - __bfloat162float(h));
}

__device__ __forceinline__ void cp16(void* dst, const void* src) {
    unsigned u = (unsigned)__cvta_generic_to_shared(dst);
    asm volatile("cp.async.cg.shared.global [%0], [%1], 16;\n" ::"r"(u), "l"(src));
}
__device__ __forceinline__ void cp_commit() { asm volatile("cp.async.commit_group;\n"); }
template <int N> __device__ __forceinline__ void cp_wait() {
    asm volatile("cp.async.wait_group %0;\n" ::"n"(N));
}

typedef wmma::fragment<wmma::matrix_a, 16, 16, 16, __nv_bfloat16, wmma::row_major> FragA;
typedef wmma::fragment<wmma::matrix_b, 16, 16, 16, __nv_bfloat16, wmma::col_major> FragB;
typedef wmma::fragment<wmma::accumulator, 16, 16, 16, float> FragC;

// C[n][m] = sum_k W[n][k] * X[m][k] + bias[n], written transposed into g_qkv.
__global__ __launch_bounds__(256) void qkv_gemm(const float* __restrict__ bias) {
    __shared__ __nv_bfloat16 sW[2][2][128 * 16];  // [buf][hi/lo][n*16+k]
    __shared__ __nv_bfloat16 sX[2][2][128 * 16];  // [buf][hi/lo][m*16+k]
    __shared__ float sStage[8][256];

    const int m0 = blockIdx.x * 128, n0 = blockIdx.y * 128;
    const int t = threadIdx.x, row = t >> 1, half = t & 1;
    const int goffW = (n0 + row) * KDIM + half * 8;
    const int soff = row * 16 + half * 8;
    const size_t goffX = (size_t)(m0 + row) * KDIM + half * 8;

    FragC acc[2][4];
#pragma unroll
    for (int i = 0; i < 2; i++)
#pragma unroll
        for (int j = 0; j < 4; j++) wmma::fill_fragment(acc[i][j], 0.0f);

    // prologue: stage 0, k0 = 0
    cp16(&sW[0][0][soff], g_Wh + goffW);
    cp16(&sW[0][1][soff], g_Wl + goffW);
    cp16(&sX[0][0][soff], g_Xh + goffX);
    cp16(&sX[0][1][soff], g_Xl + goffX);
    cp_commit();

    const int wid = t >> 5, wn = wid & 3, wm = wid >> 2;

    for (int kt = 0; kt < 64; kt++) {
        int buf = kt & 1;
        if (kt + 1 < 64) {
            int k0 = (kt + 1) * 16, nb = (kt + 1) & 1;
            cp16(&sW[nb][0][soff], g_Wh + goffW + k0);
            cp16(&sW[nb][1][soff], g_Wl + goffW + k0);
            cp16(&sX[nb][0][soff], g_Xh + goffX + k0);
            cp16(&sX[nb][1][soff], g_Xl + goffX + k0);
            cp_commit();
            cp_wait<1>();
        } else {
            cp_wait<0>();
        }
        __syncthreads();

        FragA ah[2], al[2];
        FragB bh[4], bl[4];
#pragma unroll
        for (int i = 0; i < 2; i++) {
            wmma::load_matrix_sync(ah[i], &sW[buf][0][(wn * 32 + i * 16) * 16], 16);
            wmma::load_matrix_sync(al[i], &sW[buf][1][(wn * 32 + i * 16) * 16], 16);
        }
#pragma unroll
        for (int j = 0; j < 4; j++) {
            wmma::load_matrix_sync(bh[j], &sX[buf][0][(wm * 64 + j * 16) * 16], 16);
            wmma::load_matrix_sync(bl[j], &sX[buf][1][(wm * 64 + j * 16) * 16], 16);
        }
#pragma unroll
        for (int i = 0; i < 2; i++)
#pragma unroll
            for (int j = 0; j < 4; j++) {
                wmma::mma_sync(acc[i][j], ah[i], bh[j], acc[i][j]);
                wmma::mma_sync(acc[i][j], ah[i], bl[j], acc[i][j]);
                wmma::mma_sync(acc[i][j], al[i], bh[j], acc[i][j]);
            }
        __syncthreads();
    }

    // epilogue: bias + transposed scatter  g_qkv[(h*4+b)*192+j][s]
    const int lane = t & 31, bidx = m0 >> 12;
#pragma unroll
    for (int i = 0; i < 2; i++)
#pragma unroll
        for (int j = 0; j < 4; j++) {
            wmma::store_matrix_sync(&sStage[wid][0], acc[i][j], 16, wmma::mem_row_major);
            __syncwarp();
            int n = n0 + wn * 32 + i * 16 + (lane >> 1);
            int h = n / 192, jj = n % 192;
            int s = (m0 & 4095) + wm * 64 + j * 16 + ((lane & 1) << 3);
            float bv = bias[n];
            float* dst = g_qkv + (size_t)((h * 4 + bidx) * 192 + jj) * 4096 + s;
            const float* src = &sStage[wid][(lane >> 1) * 16 + ((lane & 1) << 3)];
#pragma unroll
            for (int cc = 0; cc < 8; cc++) dst[cc] = src[cc] + bv;
            __syncwarp();
        }
}

// RoPE on q (j<64) and k (64<=j<128): only s<32; angle = d * theta^(-2i/32)
__global__ void rope_kernel() {
    int idx = blockIdx.x * blockDim.x + threadIdx.x;  // 131072 total
    int i = idx & 15;
    int d = (idx >> 4) & 63;
    int part = (idx >> 10) & 1;
    int hb = idx >> 11;
    float* p = g_qkv + (size_t)(hb * 192 + part * 64 + d) * 4096;
    double ang = (double)d * exp(-((double)(2 * i) / 32.0) * log(10000.0));
    double sv, cv;
    sincos(ang, &sv, &cv);
    float a0 = p[2 * i], a1 = p[2 * i + 1];
    p[2 * i] = (float)(a0 * cv - a1 * sv);
    p[2 * i + 1] = (float)(a1 * cv + a0 * sv);
}

// scores partials: g_part[chunk][hb][d][e] = 0.125 * sum_{s in chunk} q[d][s]*k[e][s]
__global__ __launch_bounds__(256) void scores_kernel() {
    __shared__ float sQ[64][65], sK[64][65];
    int hb = blockIdx.y, chunk = blockIdx.x, t = threadIdx.x;
    const float* q = g_qkv + (size_t)hb * 192 * 4096;
    const float* k = q + (size_t)64 * 4096;
    int td = (t >> 4) << 2, te = (t & 15) << 2;
    float acc[4][4] = {};
    for (int s0 = chunk * 512; s0 < chunk * 512 + 512; s0 += 64) {
#pragma unroll
        for (int it = 0; it < 16; it++) {
            int r = (t >> 6) + (it << 2), c = t & 63;
            sQ[r][c] = q[(size_t)r * 4096 + s0 + c];
            sK[r][c] = k[(size_t)r * 4096 + s0 + c];
        }
        __syncthreads();
#pragma unroll 4
        for (int sc = 0; sc < 64; sc++) {
            float qa[4], ka[4];
#pragma unroll
            for (int a = 0; a < 4; a++) { qa[a] = sQ[td + a][sc]; ka[a] = sK[te + a][sc]; }
#pragma unroll
            for (int a = 0; a < 4; a++)
#pragma unroll
                for (int bb = 0; bb < 4; bb++) acc[a][bb] += qa[a] * ka[bb];
        }
        __syncthreads();
    }
#pragma unroll
    for (int a = 0; a < 4; a++)
#pragma unroll
        for (int bb = 0; bb < 4; bb++)
            g_part[((size_t)(chunk * 64 + hb) * 64 + td + a) * 64 + te + bb] = acc[a][bb] * 0.125f;
}

// softmax over e: one warp per (hb,d) row; reduce 8 chunk partials first.
__global__ __launch_bounds__(256) void softmax_kernel() {
    int w = threadIdx.x >> 5, lane = threadIdx.x & 31;
    int r = blockIdx.x * 8 + w;  // 0..4095
    int hb = r >> 6, d = r & 63;
    float v0 = 0.f, v1 = 0.f;
#pragma unroll
    for (int c = 0; c < 8; c++) {
        const float* p = g_part + ((size_t)(c * 64 + hb) * 64 + d) * 64;
        v0 += p[lane];
        v1 += p[lane + 32];
    }
    float m = fmaxf(v0, v1);
#pragma unroll
    for (int o = 16; o > 0; o >>= 1) m = fmaxf(m, __shfl_xor_sync(0xffffffffu, m, o));
    float p0 = expf(v0 - m), p1 = expf(v1 - m);
    float sum = p0 + p1;
#pragma unroll
    for (int o = 16; o > 0; o >>= 1) sum += __shfl_xor_sync(0xffffffffu, sum, o);
    float inv = 1.0f / sum;
    float* dst = g_probs + (size_t)r * 64;
    dst[lane] = p0 * inv;
    dst[lane + 32] = p1 * inv;
}

// out[d][s] = sum_e probs[d][e]*v[e][s]; write to d_out[((h*64+d)*4+b)*4096+s]
__global__ __launch_bounds__(256) void out_kernel(float* __restrict__ out) {
    __shared__ float sP[64 * 64];
    int hb = blockIdx.y, t = threadIdx.x;
#pragma unroll
    for (int i = 0; i < 16; i++) sP[t + 256 * i] = g_probs[(size_t)hb * 4096 + t + 256 * i];
    __syncthreads();
    int s = blockIdx.x * 128 + (t & 127);
    int dh = t >> 7;  // 0 or 1 -> d in [0,32) or [32,64)
    const float* v = g_qkv + (size_t)(hb * 192 + 128) * 4096;
    float acc[32] = {};
    for (int e = 0; e < 64; e += 4) {
        float v0 = v[(size_t)e * 4096 + s];
        float v1 = v[(size_t)(e + 1) * 4096 + s];
        float v2 = v[(size_t)(e + 2) * 4096 + s];
        float v3 = v[(size_t)(e + 3) * 4096 + s];
#pragma unroll
        for (int d = 0; d < 32; d++) {
            const float4 p = *(const float4*)&sP[(dh * 32 + d) * 64 + e];
            acc[d] += p.x * v0 + p.y * v1 + p.z * v2 + p.w * v3;
        }
    }
    int h = hb >> 2, b = hb & 3;
#pragma unroll
    for (int d = 0; d < 32; d++) {
        int dd = dh * 32 + d;
        out[(size_t)((h * 64 + dd) * 4 + b) * 4096 + s] = acc[d];
    }
}

extern "C" void kernel_launch(void* const* d_in, const int* in_sizes, int n_in,
                              void* d_out, int out_size) {
    const float* x = (const float*)d_in[0];
    const float* W = (const float*)d_in[1];
    const float* bias = (const float*)d_in[2];
    float* out = (float*)d_out;

    split_x<<<65536, 256>>>(x);
    split_w<<<12288, 256>>>(W);
    qkv_gemm<<<dim3(128, 24), 256>>>(bias);
    rope_kernel<<<512, 256>>>();
    scores_kernel<<<dim3(8, 64), 256>>>();
    softmax_kernel<<<512, 256>>>();
    out_kernel<<<dim3(32, 64), 256>>>(out);
}